// round 10
// baseline (speedup 1.0000x reference)
#include <cuda_runtime.h>
#include <cuda_fp16.h>
#include <cstdint>

#define C_      512
#define C2H     (C_ / 2)           // half2 units per spatial position (256)
#define HF      64
#define WF      256
#define P_      (HF * WF)          // 16384 spatial positions
#define NPOS    49                 // 7x7 samples
#define CH_BLK  256                // channels per block (box split in halves)
#define TILE_FLOATS (CH_BLK * NPOS)               // 12544 floats = 50176 bytes
#define SMEM_BYTES  (2 * NPOS * 16 + TILE_FLOATS * 4)  // 1568 + 50176 = 51744

// Transposed feats in fp16: (Hf*Wf, C). Halves gather bytes through L1/L2.
__device__ __half g_featsT16[P_ * C_];

// ---------------------------------------------------------------------------
// Kernel 1: tiled transpose feats (C, P) fp32 -> featsT (P, C) fp16.
// ---------------------------------------------------------------------------
__global__ void transpose_kernel(const float* __restrict__ in) {
    __shared__ float tile[32][33];
    int p  = blockIdx.x * 32 + threadIdx.x;   // spatial index (coalesced read)
    int cb = blockIdx.y * 32;
#pragma unroll
    for (int j = 0; j < 4; j++)
        tile[threadIdx.y + j * 8][threadIdx.x] = in[(cb + threadIdx.y + j * 8) * P_ + p];
    __syncthreads();
    int pp = blockIdx.x * 32 + threadIdx.y;
    int cc = cb + threadIdx.x;                // channel index (coalesced write)
#pragma unroll
    for (int j = 0; j < 4; j++)
        g_featsT16[(size_t)(pp + j * 8) * C_ + cc] =
            __float2half_rn(tile[threadIdx.x][threadIdx.y + j * 8]);
}

// ---------------------------------------------------------------------------
// Gather a chunk of LEN positions with register accumulation, then one STS
// burst (smem alias fence only at chunk ends). fp16 half2 loads, fp32 math.
// ---------------------------------------------------------------------------
template <int LEN>
__device__ __forceinline__ void gather_chunk(const __half2* __restrict__ Fg,
                                             const int4*    __restrict__ so,
                                             const float4*  __restrict__ swt,
                                             float* __restrict__ sp, int kk) {
    float a0[LEN], a1[LEN];
#pragma unroll
    for (int j = 0; j < LEN; j++) {
        int4   o = so[kk + j];
        float4 w = swt[kk + j];
        float2 a  = __half22float2(__ldg(Fg + o.x));
        float2 bb = __half22float2(__ldg(Fg + o.y));
        float2 cc = __half22float2(__ldg(Fg + o.z));
        float2 dd = __half22float2(__ldg(Fg + o.w));
        a0[j] = w.x * a.x + w.y * bb.x + w.z * cc.x + w.w * dd.x;
        a1[j] = w.x * a.y + w.y * bb.y + w.z * cc.y + w.w * dd.y;
    }
#pragma unroll
    for (int j = 0; j < LEN; j++) {
        sp[kk + j]        = a0[j];
        sp[NPOS + kk + j] = a1[j];
    }
}

// ---------------------------------------------------------------------------
// Kernel 2: one block = (box, channel-half). 256 threads, 256 channels.
//   Phase 0: 49 sample offsets (half2 units, ch-half folded in) + weights.
//   Phase 1: thread t: g = t&127 -> channels {2g,2g+1}; q = t>>7 -> 25-pos
//            half (ps = q*24; pos 24 duplicated, identical value).
//            Two register-accumulated chunks (12+13 positions).
//   Phase 2: one 1D bulk TMA store of the packed 50,176-byte half-tile.
// ---------------------------------------------------------------------------
__global__ __launch_bounds__(256, 4)
void roi_kernel(const float* __restrict__ boxes,
                const int* __restrict__ imhp,
                const int* __restrict__ imwp,
                float* __restrict__ out) {
    extern __shared__ unsigned char smem_raw[];
    int4*   s_off = (int4*)smem_raw;                       // 49 x int4 (half2-unit offsets)
    float4* s_w   = (float4*)(smem_raw + NPOS * 16);       // 49 x float4 (corner weights)
    float*  stage = (float*)(smem_raw + 2 * NPOS * 16);    // packed (256,49) tile

    const int bh = blockIdx.x;
    const int b  = bh >> 1;
    const int ch0h = (bh & 1) * (CH_BLK / 2);              // half2-unit channel base (0|128)
    const int t = threadIdx.x;

    if (t < NPOS) {
        float xc = boxes[b * 4 + 0], yc = boxes[b * 4 + 1];
        float w  = boxes[b * 4 + 2], h  = boxes[b * 4 + 3];
        int imh = *imhp, imw = *imwp;
        float inv_w = 1.f / (float)(imw - 1);
        float inv_h = 1.f / (float)(imh - 1);
        int iy = t / 7, ix = t - iy * 7;
        float txv = -1.f + (float)ix * (2.f / 6.f);
        float tyv = -1.f + (float)iy * (2.f / 6.f);
        float gx = (2.f * xc - (float)(imw - 1)) * inv_w + (w * inv_w) * txv;
        float gy = (2.f * yc - (float)(imh - 1)) * inv_h + (h * inv_h) * tyv;
        float px = (gx + 1.f) * 0.5f * (float)(WF - 1);
        float py = (gy + 1.f) * 0.5f * (float)(HF - 1);
        float x0f = floorf(px), y0f = floorf(py);
        float fx = px - x0f,   fy = py - y0f;
        // zero-padding outside the feature map: weight *= validity
        float vx0 = (x0f >=  0.f && x0f <= (float)(WF - 1)) ? 1.f : 0.f;
        float vx1 = (x0f >= -1.f && x0f <= (float)(WF - 2)) ? 1.f : 0.f;
        float vy0 = (y0f >=  0.f && y0f <= (float)(HF - 1)) ? 1.f : 0.f;
        float vy1 = (y0f >= -1.f && y0f <= (float)(HF - 2)) ? 1.f : 0.f;
        float wx0 = (1.f - fx) * vx0, wx1 = fx * vx1;
        float wy0 = (1.f - fy) * vy0, wy1 = fy * vy1;
        int cx0 = (int)fminf(fmaxf(x0f,       0.f), (float)(WF - 1));
        int cx1 = (int)fminf(fmaxf(x0f + 1.f, 0.f), (float)(WF - 1));
        int cy0 = (int)fminf(fmaxf(y0f,       0.f), (float)(HF - 1));
        int cy1 = (int)fminf(fmaxf(y0f + 1.f, 0.f), (float)(HF - 1));
        // offsets in half2 units, channel-half base folded in
        s_off[t] = make_int4((cy0 * WF + cx0) * C2H + ch0h,
                             (cy0 * WF + cx1) * C2H + ch0h,
                             (cy1 * WF + cx0) * C2H + ch0h,
                             (cy1 * WF + cx1) * C2H + ch0h);
        s_w[t] = make_float4(wy0 * wx0, wy0 * wx1, wy1 * wx0, wy1 * wx1);
    }
    __syncthreads();

    // Phase 1: 25 positions per half, two register-accumulated chunks (12+13).
    const int g  = t & 127;
    const int q  = t >> 7;
    const int ps = q * 24;                                  // 0 or 24 (pos 24 overlap)
    const __half2* __restrict__ Fg = (const __half2*)g_featsT16 + g;
    const int4*    __restrict__ so  = s_off + ps;
    const float4*  __restrict__ swt = s_w + ps;
    float* sp = stage + (2 * g) * NPOS + ps;

    gather_chunk<12>(Fg, so, swt, sp, 0);
    gather_chunk<13>(Fg, so, swt, sp, 12);

    // Make generic-proxy smem writes visible to the async (TMA) proxy.
    __syncthreads();
    asm volatile("fence.proxy.async.shared::cta;" ::: "memory");

    // Phase 2: one 1D bulk TMA store of the packed 50,176-byte half-tile.
    if (t == 0) {
        uint32_t saddr;
        asm("{ .reg .u64 tmp; cvta.to.shared.u64 tmp, %1; cvt.u32.u64 %0, tmp; }"
            : "=r"(saddr) : "l"(stage));
        float* gdst = out + (size_t)bh * TILE_FLOATS;
        asm volatile(
            "cp.async.bulk.global.shared::cta.bulk_group [%0], [%1], %2;"
            :: "l"(gdst), "r"(saddr), "n"(TILE_FLOATS * 4) : "memory");
        asm volatile("cp.async.bulk.commit_group;" ::: "memory");
        asm volatile("cp.async.bulk.wait_group 0;" ::: "memory");
    }
}

extern "C" void kernel_launch(void* const* d_in, const int* in_sizes, int n_in,
                              void* d_out, int out_size) {
    const float* feats = (const float*)d_in[0];
    const float* boxes = (const float*)d_in[1];
    const int*   imh   = (const int*)d_in[2];
    const int*   imw   = (const int*)d_in[3];
    float*       out   = (float*)d_out;

    int B = in_sizes[1] / 4;

    transpose_kernel<<<dim3(P_ / 32, C_ / 32), dim3(32, 8)>>>(feats);

    cudaFuncSetAttribute(roi_kernel, cudaFuncAttributeMaxDynamicSharedMemorySize, SMEM_BYTES);
    roi_kernel<<<B * 2, 256, SMEM_BYTES>>>(boxes, imh, imw, out);
}

// round 11
// speedup vs baseline: 1.0034x; 1.0034x over previous
#include <cuda_runtime.h>
#include <cuda_fp16.h>
#include <cstdint>

#define C_      512
#define C2H     (C_ / 2)           // half2 units per spatial position (256)
#define HF      64
#define WF      256
#define P_      (HF * WF)          // 16384 spatial positions
#define NPOS    49                 // 7x7 samples
#define CH_BLK  256                // channels per block (box split in halves)
#define TILE_FLOATS (CH_BLK * NPOS)               // 12544 floats = 50176 bytes
#define SMEM_BYTES  (2 * NPOS * 16 + TILE_FLOATS * 4)  // 1568 + 50176 = 51744

// Transposed feats in fp16: (Hf*Wf, C). Halves gather bytes through L1/L2.
__device__ __half g_featsT16[P_ * C_];

// ---------------------------------------------------------------------------
// Kernel 1: tiled transpose feats (C, P) fp32 -> featsT (P, C) fp16.
// ---------------------------------------------------------------------------
__global__ void transpose_kernel(const float* __restrict__ in) {
    __shared__ float tile[32][33];
    int p  = blockIdx.x * 32 + threadIdx.x;   // spatial index (coalesced read)
    int cb = blockIdx.y * 32;
#pragma unroll
    for (int j = 0; j < 4; j++)
        tile[threadIdx.y + j * 8][threadIdx.x] = in[(cb + threadIdx.y + j * 8) * P_ + p];
    __syncthreads();
    int pp = blockIdx.x * 32 + threadIdx.y;
    int cc = cb + threadIdx.x;                // channel index (coalesced write)
#pragma unroll
    for (int j = 0; j < 4; j++)
        g_featsT16[(size_t)(pp + j * 8) * C_ + cc] =
            __float2half_rn(tile[threadIdx.x][threadIdx.y + j * 8]);
}

// ---------------------------------------------------------------------------
// Gather a chunk of LEN positions. Bilinear combine in native half2
// (1 HMUL2 + 3 HFMA2 per position), convert the result once, STS burst.
// ---------------------------------------------------------------------------
template <int LEN>
__device__ __forceinline__ void gather_chunk(const __half2* __restrict__ Fg,
                                             const int4*    __restrict__ so,
                                             const int4*    __restrict__ swh,
                                             float* __restrict__ sp, int kk) {
    __half2 acc[LEN];
#pragma unroll
    for (int j = 0; j < LEN; j++) {
        int4 o  = so[kk + j];
        int4 wv = swh[kk + j];                 // 4 duplicated-half2 weights
        __half2 w0 = *reinterpret_cast<__half2*>(&wv.x);
        __half2 w1 = *reinterpret_cast<__half2*>(&wv.y);
        __half2 w2 = *reinterpret_cast<__half2*>(&wv.z);
        __half2 w3 = *reinterpret_cast<__half2*>(&wv.w);
        __half2 a = __hmul2(w0, __ldg(Fg + o.x));
        a = __hfma2(w1, __ldg(Fg + o.y), a);
        a = __hfma2(w2, __ldg(Fg + o.z), a);
        acc[j] = __hfma2(w3, __ldg(Fg + o.w), a);
    }
    // Convert + store. Row0 (channel 2g) is 8B-aligned at even pos -> paired
    // STS.64; row1 (channel 2g+1, offset +49 floats) is odd -> scalar STS.
#pragma unroll
    for (int j = 0; j + 1 < LEN; j += 2) {
        float2 f0 = __half22float2(acc[j]);
        float2 f1 = __half22float2(acc[j + 1]);
        *reinterpret_cast<float2*>(sp + kk + j) = make_float2(f0.x, f1.x);
        sp[NPOS + kk + j]     = f0.y;
        sp[NPOS + kk + j + 1] = f1.y;
    }
    if (LEN & 1) {
        int j = LEN - 1;
        float2 f = __half22float2(acc[j]);
        sp[kk + j]        = f.x;
        sp[NPOS + kk + j] = f.y;
    }
}

// ---------------------------------------------------------------------------
// Kernel 2: one block = (box, channel-half). 256 threads, 256 channels.
//   Phase 0: 49 sample offsets (half2 units) + weights as duplicated half2.
//   Phase 1: thread t: g = t&127 -> channels {2g,2g+1}; q = t>>7 -> 25-pos
//            half (ps = q*24; pos 24 duplicated, identical value).
//   Phase 2: one 1D bulk TMA store of the packed 50,176-byte half-tile.
// ---------------------------------------------------------------------------
__global__ __launch_bounds__(256, 4)
void roi_kernel(const float* __restrict__ boxes,
                const int* __restrict__ imhp,
                const int* __restrict__ imwp,
                float* __restrict__ out) {
    extern __shared__ unsigned char smem_raw[];
    int4* s_off = (int4*)smem_raw;                         // 49 x int4 (half2-unit offsets)
    int4* s_wh  = (int4*)(smem_raw + NPOS * 16);           // 49 x 4 duplicated half2 weights
    float* stage = (float*)(smem_raw + 2 * NPOS * 16);     // packed (256,49) fp32 tile

    const int bh = blockIdx.x;
    const int b  = bh >> 1;
    const int ch0h = (bh & 1) * (CH_BLK / 2);              // half2-unit channel base (0|128)
    const int t = threadIdx.x;

    if (t < NPOS) {
        float xc = boxes[b * 4 + 0], yc = boxes[b * 4 + 1];
        float w  = boxes[b * 4 + 2], h  = boxes[b * 4 + 3];
        int imh = *imhp, imw = *imwp;
        float inv_w = 1.f / (float)(imw - 1);
        float inv_h = 1.f / (float)(imh - 1);
        int iy = t / 7, ix = t - iy * 7;
        float txv = -1.f + (float)ix * (2.f / 6.f);
        float tyv = -1.f + (float)iy * (2.f / 6.f);
        float gx = (2.f * xc - (float)(imw - 1)) * inv_w + (w * inv_w) * txv;
        float gy = (2.f * yc - (float)(imh - 1)) * inv_h + (h * inv_h) * tyv;
        float px = (gx + 1.f) * 0.5f * (float)(WF - 1);
        float py = (gy + 1.f) * 0.5f * (float)(HF - 1);
        float x0f = floorf(px), y0f = floorf(py);
        float fx = px - x0f,   fy = py - y0f;
        // zero-padding outside the feature map: weight *= validity
        float vx0 = (x0f >=  0.f && x0f <= (float)(WF - 1)) ? 1.f : 0.f;
        float vx1 = (x0f >= -1.f && x0f <= (float)(WF - 2)) ? 1.f : 0.f;
        float vy0 = (y0f >=  0.f && y0f <= (float)(HF - 1)) ? 1.f : 0.f;
        float vy1 = (y0f >= -1.f && y0f <= (float)(HF - 2)) ? 1.f : 0.f;
        float wx0 = (1.f - fx) * vx0, wx1 = fx * vx1;
        float wy0 = (1.f - fy) * vy0, wy1 = fy * vy1;
        int cx0 = (int)fminf(fmaxf(x0f,       0.f), (float)(WF - 1));
        int cx1 = (int)fminf(fmaxf(x0f + 1.f, 0.f), (float)(WF - 1));
        int cy0 = (int)fminf(fmaxf(y0f,       0.f), (float)(HF - 1));
        int cy1 = (int)fminf(fmaxf(y0f + 1.f, 0.f), (float)(HF - 1));
        // offsets in half2 units, channel-half base folded in
        s_off[t] = make_int4((cy0 * WF + cx0) * C2H + ch0h,
                             (cy0 * WF + cx1) * C2H + ch0h,
                             (cy1 * WF + cx0) * C2H + ch0h,
                             (cy1 * WF + cx1) * C2H + ch0h);
        // duplicated-half2 weights, packed as int4
        __half2 hw0 = __float2half2_rn(wy0 * wx0);
        __half2 hw1 = __float2half2_rn(wy0 * wx1);
        __half2 hw2 = __float2half2_rn(wy1 * wx0);
        __half2 hw3 = __float2half2_rn(wy1 * wx1);
        s_wh[t] = make_int4(*reinterpret_cast<int*>(&hw0),
                            *reinterpret_cast<int*>(&hw1),
                            *reinterpret_cast<int*>(&hw2),
                            *reinterpret_cast<int*>(&hw3));
    }
    __syncthreads();

    // Phase 1: 25 positions per half, two register-accumulated chunks (12+13).
    const int g  = t & 127;
    const int q  = t >> 7;
    const int ps = q * 24;                                  // 0 or 24 (pos 24 overlap)
    const __half2* __restrict__ Fg = (const __half2*)g_featsT16 + g;
    const int4*    __restrict__ so  = s_off + ps;
    const int4*    __restrict__ swh = s_wh + ps;
    float* sp = stage + (2 * g) * NPOS + ps;

    gather_chunk<12>(Fg, so, swh, sp, 0);
    gather_chunk<13>(Fg, so, swh, sp, 12);

    // Make generic-proxy smem writes visible to the async (TMA) proxy.
    __syncthreads();
    asm volatile("fence.proxy.async.shared::cta;" ::: "memory");

    // Phase 2: one 1D bulk TMA store of the packed 50,176-byte half-tile.
    if (t == 0) {
        uint32_t saddr;
        asm("{ .reg .u64 tmp; cvta.to.shared.u64 tmp, %1; cvt.u32.u64 %0, tmp; }"
            : "=r"(saddr) : "l"(stage));
        float* gdst = out + (size_t)bh * TILE_FLOATS;
        asm volatile(
            "cp.async.bulk.global.shared::cta.bulk_group [%0], [%1], %2;"
            :: "l"(gdst), "r"(saddr), "n"(TILE_FLOATS * 4) : "memory");
        asm volatile("cp.async.bulk.commit_group;" ::: "memory");
        asm volatile("cp.async.bulk.wait_group 0;" ::: "memory");
    }
}

extern "C" void kernel_launch(void* const* d_in, const int* in_sizes, int n_in,
                              void* d_out, int out_size) {
    const float* feats = (const float*)d_in[0];
    const float* boxes = (const float*)d_in[1];
    const int*   imh   = (const int*)d_in[2];
    const int*   imw   = (const int*)d_in[3];
    float*       out   = (float*)d_out;

    int B = in_sizes[1] / 4;

    transpose_kernel<<<dim3(P_ / 32, C_ / 32), dim3(32, 8)>>>(feats);

    cudaFuncSetAttribute(roi_kernel, cudaFuncAttributeMaxDynamicSharedMemorySize, SMEM_BYTES);
    roi_kernel<<<B * 2, 256, SMEM_BYTES>>>(boxes, imh, imw, out);
}

// round 12
// speedup vs baseline: 1.0588x; 1.0552x over previous
#include <cuda_runtime.h>
#include <cuda_fp16.h>
#include <cstdint>

#define C_      512
#define C2H     (C_ / 2)           // half2 units per spatial position (256)
#define HF      64
#define WF      256
#define P_      (HF * WF)          // 16384 spatial positions
#define NPOS    49                 // 7x7 samples
#define CH_BLK  128                // channels per block (box split in quarters)
#define TILE_FLOATS (CH_BLK * NPOS)               // 6272 floats = 25088 bytes
#define SMEM_BYTES  (2 * NPOS * 16 + TILE_FLOATS * 4)  // 1568 + 25088 = 26656

// Transposed feats in fp16: (Hf*Wf, C). Halves gather bytes + L2 footprint.
__device__ __half g_featsT16[P_ * C_];

// ---------------------------------------------------------------------------
// Kernel 1: tiled transpose feats (C, P) fp32 -> featsT (P, C) fp16.
// ---------------------------------------------------------------------------
__global__ void transpose_kernel(const float* __restrict__ in) {
    __shared__ float tile[32][33];
    int p  = blockIdx.x * 32 + threadIdx.x;   // spatial index (coalesced read)
    int cb = blockIdx.y * 32;
#pragma unroll
    for (int j = 0; j < 4; j++)
        tile[threadIdx.y + j * 8][threadIdx.x] = in[(cb + threadIdx.y + j * 8) * P_ + p];
    __syncthreads();
    int pp = blockIdx.x * 32 + threadIdx.y;
    int cc = cb + threadIdx.x;                // channel index (coalesced write)
#pragma unroll
    for (int j = 0; j < 4; j++)
        g_featsT16[(size_t)(pp + j * 8) * C_ + cc] =
            __float2half_rn(tile[threadIdx.x][threadIdx.y + j * 8]);
}

// ---------------------------------------------------------------------------
// Gather a chunk of LEN positions. Bilinear combine in native half2
// (1 HMUL2 + 3 HFMA2 per position), convert the result once, STS burst.
// ---------------------------------------------------------------------------
template <int LEN>
__device__ __forceinline__ void gather_chunk(const __half2* __restrict__ Fg,
                                             const int4*    __restrict__ so,
                                             const int4*    __restrict__ swh,
                                             float* __restrict__ sp, int kk) {
    __half2 acc[LEN];
#pragma unroll
    for (int j = 0; j < LEN; j++) {
        int4 o  = so[kk + j];
        int4 wv = swh[kk + j];                 // 4 duplicated-half2 weights
        __half2 w0 = *reinterpret_cast<__half2*>(&wv.x);
        __half2 w1 = *reinterpret_cast<__half2*>(&wv.y);
        __half2 w2 = *reinterpret_cast<__half2*>(&wv.z);
        __half2 w3 = *reinterpret_cast<__half2*>(&wv.w);
        __half2 a = __hmul2(w0, __ldg(Fg + o.x));
        a = __hfma2(w1, __ldg(Fg + o.y), a);
        a = __hfma2(w2, __ldg(Fg + o.z), a);
        acc[j] = __hfma2(w3, __ldg(Fg + o.w), a);
    }
#pragma unroll
    for (int j = 0; j < LEN; j++) {
        float2 f = __half22float2(acc[j]);
        sp[kk + j]        = f.x;
        sp[NPOS + kk + j] = f.y;
    }
}

// ---------------------------------------------------------------------------
// Kernel 2: one block = (box, channel-quarter). 256 threads, 128 channels.
//   Phase 0: 49 sample offsets (half2 units) + weights as duplicated half2.
//   Phase 1: thread t: g = t&63 -> channels {2g,2g+1}; q = t>>6 -> 13-pos
//            group (ps = q*12; boundary positions duplicated, identical).
//   Phase 2: one 1D bulk TMA store of the packed 25,088-byte quarter-tile.
//   6 blocks/SM (42 regs): high occupancy; fp16 feats keep the concurrent
//   gather footprint (~44 MB chip-wide) L2-resident (R5 lesson, fp16-adjusted).
// ---------------------------------------------------------------------------
__global__ __launch_bounds__(256, 6)
void roi_kernel(const float* __restrict__ boxes,
                const int* __restrict__ imhp,
                const int* __restrict__ imwp,
                float* __restrict__ out) {
    extern __shared__ unsigned char smem_raw[];
    int4* s_off = (int4*)smem_raw;                         // 49 x int4 (half2-unit offsets)
    int4* s_wh  = (int4*)(smem_raw + NPOS * 16);           // 49 x 4 duplicated half2 weights
    float* stage = (float*)(smem_raw + 2 * NPOS * 16);     // packed (128,49) fp32 tile

    const int bh = blockIdx.x;
    const int b  = bh >> 2;
    const int ch0h = (bh & 3) * (CH_BLK / 2);              // half2-unit channel base
    const int t = threadIdx.x;

    if (t < NPOS) {
        float xc = boxes[b * 4 + 0], yc = boxes[b * 4 + 1];
        float w  = boxes[b * 4 + 2], h  = boxes[b * 4 + 3];
        int imh = *imhp, imw = *imwp;
        float inv_w = 1.f / (float)(imw - 1);
        float inv_h = 1.f / (float)(imh - 1);
        int iy = t / 7, ix = t - iy * 7;
        float txv = -1.f + (float)ix * (2.f / 6.f);
        float tyv = -1.f + (float)iy * (2.f / 6.f);
        float gx = (2.f * xc - (float)(imw - 1)) * inv_w + (w * inv_w) * txv;
        float gy = (2.f * yc - (float)(imh - 1)) * inv_h + (h * inv_h) * tyv;
        float px = (gx + 1.f) * 0.5f * (float)(WF - 1);
        float py = (gy + 1.f) * 0.5f * (float)(HF - 1);
        float x0f = floorf(px), y0f = floorf(py);
        float fx = px - x0f,   fy = py - y0f;
        // zero-padding outside the feature map: weight *= validity
        float vx0 = (x0f >=  0.f && x0f <= (float)(WF - 1)) ? 1.f : 0.f;
        float vx1 = (x0f >= -1.f && x0f <= (float)(WF - 2)) ? 1.f : 0.f;
        float vy0 = (y0f >=  0.f && y0f <= (float)(HF - 1)) ? 1.f : 0.f;
        float vy1 = (y0f >= -1.f && y0f <= (float)(HF - 2)) ? 1.f : 0.f;
        float wx0 = (1.f - fx) * vx0, wx1 = fx * vx1;
        float wy0 = (1.f - fy) * vy0, wy1 = fy * vy1;
        int cx0 = (int)fminf(fmaxf(x0f,       0.f), (float)(WF - 1));
        int cx1 = (int)fminf(fmaxf(x0f + 1.f, 0.f), (float)(WF - 1));
        int cy0 = (int)fminf(fmaxf(y0f,       0.f), (float)(HF - 1));
        int cy1 = (int)fminf(fmaxf(y0f + 1.f, 0.f), (float)(HF - 1));
        // offsets in half2 units, channel-quarter base folded in
        s_off[t] = make_int4((cy0 * WF + cx0) * C2H + ch0h,
                             (cy0 * WF + cx1) * C2H + ch0h,
                             (cy1 * WF + cx0) * C2H + ch0h,
                             (cy1 * WF + cx1) * C2H + ch0h);
        // duplicated-half2 weights, packed as int4
        __half2 hw0 = __float2half2_rn(wy0 * wx0);
        __half2 hw1 = __float2half2_rn(wy0 * wx1);
        __half2 hw2 = __float2half2_rn(wy1 * wx0);
        __half2 hw3 = __float2half2_rn(wy1 * wx1);
        s_wh[t] = make_int4(*reinterpret_cast<int*>(&hw0),
                            *reinterpret_cast<int*>(&hw1),
                            *reinterpret_cast<int*>(&hw2),
                            *reinterpret_cast<int*>(&hw3));
    }
    __syncthreads();

    // Phase 1: 13 positions per group (ps = q*12), chunks of 6+7.
    const int g  = t & 63;
    const int q  = t >> 6;
    const int ps = q * 12;                                  // 0,12,24,36 (overlap ok)
    const __half2* __restrict__ Fg = (const __half2*)g_featsT16 + g;
    const int4*    __restrict__ so  = s_off + ps;
    const int4*    __restrict__ swh = s_wh + ps;
    float* sp = stage + (2 * g) * NPOS + ps;

    gather_chunk<6>(Fg, so, swh, sp, 0);
    gather_chunk<7>(Fg, so, swh, sp, 6);

    // Make generic-proxy smem writes visible to the async (TMA) proxy.
    __syncthreads();
    asm volatile("fence.proxy.async.shared::cta;" ::: "memory");

    // Phase 2: one 1D bulk TMA store of the packed 25,088-byte quarter-tile.
    if (t == 0) {
        uint32_t saddr;
        asm("{ .reg .u64 tmp; cvta.to.shared.u64 tmp, %1; cvt.u32.u64 %0, tmp; }"
            : "=r"(saddr) : "l"(stage));
        float* gdst = out + (size_t)bh * TILE_FLOATS;
        asm volatile(
            "cp.async.bulk.global.shared::cta.bulk_group [%0], [%1], %2;"
            :: "l"(gdst), "r"(saddr), "n"(TILE_FLOATS * 4) : "memory");
        asm volatile("cp.async.bulk.commit_group;" ::: "memory");
        asm volatile("cp.async.bulk.wait_group 0;" ::: "memory");
    }
}

extern "C" void kernel_launch(void* const* d_in, const int* in_sizes, int n_in,
                              void* d_out, int out_size) {
    const float* feats = (const float*)d_in[0];
    const float* boxes = (const float*)d_in[1];
    const int*   imh   = (const int*)d_in[2];
    const int*   imw   = (const int*)d_in[3];
    float*       out   = (float*)d_out;

    int B = in_sizes[1] / 4;

    transpose_kernel<<<dim3(P_ / 32, C_ / 32), dim3(32, 8)>>>(feats);

    cudaFuncSetAttribute(roi_kernel, cudaFuncAttributeMaxDynamicSharedMemorySize, SMEM_BYTES);
    roi_kernel<<<B * 4, 256, SMEM_BYTES>>>(boxes, imh, imw, out);
}